// round 15
// baseline (speedup 1.0000x reference)
#include <cuda_runtime.h>
#include <cuda_fp16.h>
#include <math.h>
#include <stdint.h>

#define B_ 256
#define T_ 256
#define F_ 128
#define H_ 512
#define BT (B_*T_)
#define NCTA 64

// ---------------- scratch (static __device__ allocations) -------------------
__device__ float g_xm[(size_t)BT * 256];        // [BT][256] = x_rep | m
__device__ float g_gamma_h[(size_t)BT * H_];    // [BT][512]
__device__ float g_gi[(size_t)BT * 1536];       // [BT][1536] gi_pre (+b_ih)
__device__ float g_W2[1536 * 256];              // [1536][256]
__device__ __half g_Wtb[2 * 32 * 96 * 512];     // [split][nb][c=g*16+jl][k] fp16
__device__ float g_h[2][B_ * H_];               // ping-pong hidden state (fp32)
__device__ __half g_abhi[2][B_ * H_];           // PING-PONG fp16 hi split of h.gamma
__device__ __half g_ablo[2][B_ * H_];           // PING-PONG fp16 lo split
__device__ int   g_flags[NCTA];
__device__ int   g_gen;

// ---------------- helpers ---------------------------------------------------
#define FMA2(d, a, b) asm("fma.rn.f32x2 %0, %1, %2, %0;" : "+l"(d) : "l"(a), "l"(b))
#define UNPK2(lo, hi, v) asm("mov.b64 {%0, %1}, %2;" : "=f"(lo), "=f"(hi) : "l"(v))

__device__ __forceinline__ uint32_t smem_to_u32(const void* p) {
    uint32_t a;
    asm("{ .reg .u64 t; cvta.to.shared.u64 t, %1; cvt.u32.u64 %0, t; }" : "=r"(a) : "l"(p));
    return a;
}

// warp-level fp16 MMA, fp32 accumulate (sm_80+, legal at plain compute_103)
#define MMA16816(d, a, b0v, b1v) \
    asm volatile("mma.sync.aligned.m16n8k16.row.col.f32.f16.f16.f32 " \
        "{%0,%1,%2,%3}, {%4,%5,%6,%7}, {%8,%9}, {%0,%1,%2,%3};" \
        : "+f"((d)[0]), "+f"((d)[1]), "+f"((d)[2]), "+f"((d)[3]) \
        : "r"((a)[0]), "r"((a)[1]), "r"((a)[2]), "r"((a)[3]), "r"(b0v), "r"(b1v))

#define LDSM4(r, addr) \
    asm volatile("ldmatrix.sync.aligned.m8n8.x4.shared.b16 {%0,%1,%2,%3}, [%4];" \
        : "=r"((r)[0]), "=r"((r)[1]), "=r"((r)[2]), "=r"((r)[3]) : "r"(addr))

// ---------------- pack kernels ---------------------------------------------
__global__ void __launch_bounds__(256) pack_w2_kernel(const float* __restrict__ W_ih) {
    int idx = blockIdx.x * 256 + threadIdx.x;       // 1536*256
    int row = idx >> 8, k = idx & 255;
    float v = (k < 128) ? W_ih[row * 768 + k] : W_ih[row * 768 + 512 + k];
    g_W2[idx] = v;
}

// fp16 split weights: g_Wtb[split][nb][c=g*16+jl][k], j = nb*16+jl
__global__ void __launch_bounds__(256) pack_wtb_kernel(const float* __restrict__ W_ih,
                                                       const float* __restrict__ W_hh) {
    int idx = blockIdx.x * 256 + threadIdx.x;       // 2*32*96*512
    int k = idx & 511;
    int r2 = idx >> 9;
    int c = r2 % 96;
    int t2 = r2 / 96;          // split*32 + nb
    int nb = t2 & 31;
    int split = t2 >> 5;
    int g = c >> 4, jl = c & 15;
    int j = nb * 16 + jl;
    float w = (g < 3) ? W_ih[(g * 512 + j) * 768 + 128 + k]
                      : W_hh[((g - 3) * 512 + j) * 512 + k];
    __half hi = __float2half_rn(w);
    if (split == 0) g_Wtb[idx] = hi;
    else            g_Wtb[idx] = __float2half_rn(w - __half2float(hi));
}

__global__ void __launch_bounds__(256) zero_h_kernel() {
    int i = blockIdx.x * 256 + threadIdx.x;         // B_*H_ = 131072
    g_h[0][i] = 0.0f;
    g_abhi[0][i] = __float2half_rn(0.0f);
    g_ablo[0][i] = __float2half_rn(0.0f);
    g_abhi[1][i] = __float2half_rn(0.0f);
    g_ablo[1][i] = __float2half_rn(0.0f);
    if (blockIdx.x == 0) {
        if (threadIdx.x < NCTA) g_flags[threadIdx.x] = 0;
        if (threadIdx.x == 0) g_gen = 0;
    }
}

// ---------------- elementwise: x_rep / m packing ----------------------------
__global__ void __launch_bounds__(256) xm_kernel(const float* __restrict__ values,
                          const float* __restrict__ masks,
                          const float* __restrict__ deltas,
                          const float* __restrict__ emean,
                          const float* __restrict__ xlocf,
                          const float* __restrict__ wx,
                          const float* __restrict__ bx) {
    int idx = blockIdx.x * 256 + threadIdx.x;       // BT*F
    int f = idx & 127;
    int r = idx >> 7;
    float d = deltas[idx];
    float a = d * wx[f] + bx[f];
    float gx = (a > 0.0f) ? expf(-a) : 1.0f;
    float m = masks[idx];
    float xh = gx * xlocf[idx] + (1.0f - gx) * emean[f];
    float xr = m * values[idx] + (1.0f - m) * xh;
    g_xm[(size_t)r * 256 + f] = xr;
    g_xm[(size_t)r * 256 + 128 + f] = m;
}

// ---------------- precompute GEMM (unchanged, proven) ------------------------
__global__ void __launch_bounds__(256) gemm_f2_kernel(const float* __restrict__ Ap,
                               const float* __restrict__ Wp,
                               const float* __restrict__ bias,
                               int which) {
    const float* __restrict__ A;
    const float* __restrict__ W;
    float* __restrict__ C;
    int N, K;
    if (which == 0) { A = Ap;   W = Wp;   C = g_gamma_h; N = 512;  K = 128; }
    else            { A = g_xm; W = g_W2; C = g_gi;      N = 1536; K = 256; }

    __shared__ __align__(16) float As[16 * 130];
    __shared__ __align__(16) float Bs[16 * 66];
    const int tid = threadIdx.x;
    const int m0 = blockIdx.y * 64;
    const int n0 = blockIdx.x * 64;
    const int lr = tid >> 2;
    const int kq = (tid & 3) << 2;
    const int ty = tid >> 4, tx = tid & 15;

    unsigned long long acc[4][2];
#pragma unroll
    for (int r = 0; r < 4; r++) { acc[r][0] = 0ull; acc[r][1] = 0ull; }

    for (int k0 = 0; k0 < K; k0 += 16) {
        float4 av = *(const float4*)(A + (size_t)(m0 + lr) * K + k0 + kq);
        float4 bv = *(const float4*)(W + (size_t)(n0 + lr) * K + k0 + kq);
        __syncthreads();
        As[(kq + 0) * 130 + 2 * lr] = av.x; As[(kq + 0) * 130 + 2 * lr + 1] = av.x;
        As[(kq + 1) * 130 + 2 * lr] = av.y; As[(kq + 1) * 130 + 2 * lr + 1] = av.y;
        As[(kq + 2) * 130 + 2 * lr] = av.z; As[(kq + 2) * 130 + 2 * lr + 1] = av.z;
        As[(kq + 3) * 130 + 2 * lr] = av.w; As[(kq + 3) * 130 + 2 * lr + 1] = av.w;
        Bs[(kq + 0) * 66 + lr] = bv.x;
        Bs[(kq + 1) * 66 + lr] = bv.y;
        Bs[(kq + 2) * 66 + lr] = bv.z;
        Bs[(kq + 3) * 66 + lr] = bv.w;
        __syncthreads();
#pragma unroll
        for (int kk = 0; kk < 16; kk++) {
            unsigned long long b01 = *(const unsigned long long*)&Bs[kk * 66 + tx * 4];
            unsigned long long b23 = *(const unsigned long long*)&Bs[kk * 66 + tx * 4 + 2];
#pragma unroll
            for (int r = 0; r < 4; r++) {
                unsigned long long ad =
                    *(const unsigned long long*)&As[kk * 130 + (ty * 4 + r) * 2];
                FMA2(acc[r][0], ad, b01);
                FMA2(acc[r][1], ad, b23);
            }
        }
    }
    const int n = n0 + tx * 4;
    float b0v = bias[n], b1v = bias[n + 1], b2v = bias[n + 2], b3v = bias[n + 3];
#pragma unroll
    for (int r = 0; r < 4; r++) {
        int m = m0 + ty * 4 + r;
        float4 v;
        UNPK2(v.x, v.y, acc[r][0]);
        UNPK2(v.z, v.w, acc[r][1]);
        v.x += b0v; v.y += b1v; v.z += b2v; v.w += b3v;
        if (which == 0) {
            v.x = (v.x > 0.0f) ? expf(-v.x) : 1.0f;
            v.y = (v.y > 0.0f) ? expf(-v.y) : 1.0f;
            v.z = (v.z > 0.0f) ? expf(-v.z) : 1.0f;
            v.w = (v.w > 0.0f) ? expf(-v.w) : 1.0f;
        }
        *(float4*)(C + (size_t)m * N + n) = v;
    }
}

// ---------------- persistent mma.sync scan kernel ----------------------------
// Grid (32, 2): nb = j-tile of 16 (96 packed gate-cols), half = 128 batch rows.
// 128 threads = 4 warps; warp w covers batch rows [b0+32w, +32) as 2 m16 tiles.
// D[128 x 96] = A[128 x 512] @ W[96 x 512]^T, fp16 hi/lo split (3 MMA terms).
// W resident in SMEM (hi at 0, lo at 98304), XOR-swizzled for ldmatrix.
// A splits are PING-PONG buffered (read parity t, write parity t+1): the
// epilogue of a fast CTA must never overwrite A data a slow CTA still reads.
#define SM_WLO 98304
#define SM_TOTAL 196608

// A-fragment load for k-chunk kc into ah/al (u32[2][4] each)
#define LOADA(kc, ah, al) do { \
    int _k = (kc) * 16 + kb_l; \
    (ah)[0][0] = *(const uint32_t*)(abh + o0 + _k); \
    (ah)[0][1] = *(const uint32_t*)(abh + o0b + _k); \
    (ah)[0][2] = *(const uint32_t*)(abh + o0 + _k + 8); \
    (ah)[0][3] = *(const uint32_t*)(abh + o0b + _k + 8); \
    (ah)[1][0] = *(const uint32_t*)(abh + o1 + _k); \
    (ah)[1][1] = *(const uint32_t*)(abh + o1b + _k); \
    (ah)[1][2] = *(const uint32_t*)(abh + o1 + _k + 8); \
    (ah)[1][3] = *(const uint32_t*)(abh + o1b + _k + 8); \
    (al)[0][0] = *(const uint32_t*)(abl + o0 + _k); \
    (al)[0][1] = *(const uint32_t*)(abl + o0b + _k); \
    (al)[0][2] = *(const uint32_t*)(abl + o0 + _k + 8); \
    (al)[0][3] = *(const uint32_t*)(abl + o0b + _k + 8); \
    (al)[1][0] = *(const uint32_t*)(abl + o1 + _k); \
    (al)[1][1] = *(const uint32_t*)(abl + o1b + _k); \
    (al)[1][2] = *(const uint32_t*)(abl + o1 + _k + 8); \
    (al)[1][3] = *(const uint32_t*)(abl + o1b + _k + 8); \
} while (0)

__global__ void __launch_bounds__(128)
scan_mma_kernel(const float* __restrict__ b_hh, float* __restrict__ out) {
    extern __shared__ char smem[];
    const uint32_t sb = smem_to_u32(smem);
    const int tid = threadIdx.x;
    const int lane = tid & 31;
    const int wid = tid >> 5;
    const int nb = blockIdx.x;
    const int half = blockIdx.y;
    const int b0 = half * 128;
    const int cta = half * 32 + nb;

    // ---- load resident W (hi/lo) into swizzled SMEM ----
    {
        const __half* Whi = g_Wtb + (size_t)nb * 49152;
        const __half* Wlo = g_Wtb + (size_t)(32 + nb) * 49152;
        for (int i = tid; i < 96 * 512; i += 128) {
            int n = i >> 9, k = i & 511;
            uint32_t boff = (uint32_t)(n * 1024 + (((k >> 3) ^ (n & 7)) << 4) + (k & 7) * 2);
            *(__half*)(smem + boff) = Whi[i];
            *(__half*)(smem + SM_WLO + boff) = Wlo[i];
        }
    }
    __syncthreads();

    // ---- hoisted lane constants ----
    const int rowA0 = b0 + wid * 32 + (lane >> 2);   // mt=0 base row
    const int rowA1 = rowA0 + 16;                    // mt=1 base row
    const size_t o0  = (size_t)rowA0 * 512;
    const size_t o0b = (size_t)(rowA0 + 8) * 512;
    const size_t o1  = (size_t)rowA1 * 512;
    const size_t o1b = (size_t)(rowA1 + 8) * 512;
    const int kb_l = (lane & 3) << 1;

    // ldmatrix lane addressing: n' = p*16 + (lane&7) + ((lane>>4)<<3)
    const int nlane = (lane & 7) + ((lane >> 4) << 3);
    const int kl = (lane >> 3) & 1;
    const int nmask = nlane & 7;
    uint32_t bbase[6];
#pragma unroll
    for (int p = 0; p < 6; p++)
        bbase[p] = sb + (uint32_t)((p * 16 + nlane) * 1024);

    // epilogue hoists: biases per (tp, lo)
    float biasv[2][2][3];
#pragma unroll
    for (int tp = 0; tp < 2; tp++)
#pragma unroll
        for (int lo = 0; lo < 2; lo++) {
            int gj = nb * 16 + ((lane & 3) << 1) + (tp << 3) + lo;
            biasv[tp][lo][0] = b_hh[gj];
            biasv[tp][lo][1] = b_hh[512 + gj];
            biasv[tp][lo][2] = b_hh[1024 + gj];
        }

    for (int t = 0; t < T_; t++) {
        const __half* __restrict__ abh = g_abhi[t & 1];
        const __half* __restrict__ abl = g_ablo[t & 1];
        __half* __restrict__ abh_w = g_abhi[(t + 1) & 1];
        __half* __restrict__ abl_w = g_ablo[(t + 1) & 1];

        float acc[2][12][4];
#pragma unroll
        for (int mt = 0; mt < 2; mt++)
#pragma unroll
            for (int nt = 0; nt < 12; nt++) {
                acc[mt][nt][0] = 0.0f; acc[mt][nt][1] = 0.0f;
                acc[mt][nt][2] = 0.0f; acc[mt][nt][3] = 0.0f;
            }

        uint32_t Ah[2][2][4], Al[2][2][4];
        LOADA(0, Ah[0], Al[0]);

#pragma unroll 2
        for (int kc = 0; kc < 32; kc++) {
            const int cb = kc & 1;
            uint32_t Bh[6][4], Bl[6][4];
            const uint32_t koff = (uint32_t)((((kc << 1) | kl) ^ nmask) << 4);
#pragma unroll
            for (int p = 0; p < 6; p++) {
                LDSM4(Bh[p], bbase[p] + koff);
                LDSM4(Bl[p], bbase[p] + SM_WLO + koff);
            }
            if (kc < 31) LOADA(kc + 1, Ah[cb ^ 1], Al[cb ^ 1]);
#pragma unroll
            for (int mt = 0; mt < 2; mt++)
#pragma unroll
                for (int nt = 0; nt < 12; nt++) {
                    const int p = nt >> 1, q = (nt & 1) << 1;
                    MMA16816(acc[mt][nt], Ah[cb][mt], Bh[p][q], Bh[p][q + 1]);
                    MMA16816(acc[mt][nt], Al[cb][mt], Bh[p][q], Bh[p][q + 1]);
                    MMA16816(acc[mt][nt], Ah[cb][mt], Bl[p][q], Bl[p][q + 1]);
                }
        }

        // ---- epilogue: thread-local gates, state update, next-step A write ----
        const float* __restrict__ hin = g_h[t & 1];
        float* __restrict__ hout = g_h[(t + 1) & 1];
#pragma unroll
        for (int mt = 0; mt < 2; mt++) {
#pragma unroll
            for (int mh = 0; mh < 2; mh++) {
                const int b = (mt ? rowA1 : rowA0) + mh * 8;
                const size_t ridx = (size_t)b * T_ + t;
                const float* __restrict__ gi = g_gi + ridx * 1536;
                const float* __restrict__ gr = g_gamma_h + ridx * 512;
#pragma unroll
                for (int tp = 0; tp < 2; tp++) {
                    const int jl0 = ((lane & 3) << 1) + (tp << 3);
                    const int gj0 = nb * 16 + jl0;
                    float hv2[2];
#pragma unroll
                    for (int lo = 0; lo < 2; lo++) {
                        const int gj = gj0 + lo;
                        const int rg = mh * 2 + lo;
                        float u0 = acc[mt][tp][rg];
                        float u1 = acc[mt][2 + tp][rg];
                        float u2 = acc[mt][4 + tp][rg];
                        float u3 = acc[mt][6 + tp][rg];
                        float u4 = acc[mt][8 + tp][rg];
                        float u5 = acc[mt][10 + tp][rg];
                        float ir  = gi[gj] + u0;
                        float iz  = gi[512 + gj] + u1;
                        float in_ = gi[1024 + gj] + u2;
                        float hr_ = u3 + biasv[tp][lo][0];
                        float hz  = u4 + biasv[tp][lo][1];
                        float hn  = u5 + biasv[tp][lo][2];
                        float hd = hin[(size_t)b * 512 + gj] * gr[gj];
                        float r = 1.0f / (1.0f + expf(-(ir + hr_)));
                        float z = 1.0f / (1.0f + expf(-(iz + hz)));
                        float n = tanhf(in_ + r * hn);
                        float hvn = (1.0f - z) * n + z * hd;
                        hout[(size_t)b * 512 + gj] = hvn;
                        out[ridx * 512 + gj] = hvn;
                        if (t == T_ - 1)
                            out[(size_t)BT * 512 + (size_t)b * 512 + gj] = hvn;
                        hv2[lo] = hvn;
                    }
                    if (t < T_ - 1) {
                        const float* grn = g_gamma_h + (ridx + 1) * 512;
                        float x0 = hv2[0] * grn[gj0];
                        float x1 = hv2[1] * grn[gj0 + 1];
                        __half h0 = __float2half_rn(x0);
                        __half h1 = __float2half_rn(x1);
                        float r0 = x0 - __half2float(h0);
                        float r1 = x1 - __half2float(h1);
                        __half l0 = __float2half_rn(r0);
                        __half l1 = __float2half_rn(r1);
                        __half2 ph = __halves2half2(h0, h1);
                        __half2 pl = __halves2half2(l0, l1);
                        *(__half2*)(abh_w + (size_t)b * 512 + gj0) = ph;
                        *(__half2*)(abl_w + (size_t)b * 512 + gj0) = pl;
                    }
                }
            }
        }

        // ---- grid barrier (64 CTAs co-resident, flag protocol) ----
        if (t < T_ - 1) {
            __syncthreads();
            if (tid == 0) {
                __threadfence();
                ((volatile int*)g_flags)[cta] = t + 1;
            }
            if (cta == 0) {
                if (tid < NCTA) {
                    while (((volatile int*)g_flags)[tid] <= t) { }
                    __threadfence();
                }
            } else {
                if (tid == 0) {
                    while (*((volatile int*)&g_gen) <= t) { }
                    __threadfence();
                }
            }
            __syncthreads();
            if (cta == 0 && tid == 0) {
                *((volatile int*)&g_gen) = t + 1;
            }
        }
    }
}

// ---------------- launch ----------------------------------------------------
extern "C" void kernel_launch(void* const* d_in, const int* in_sizes, int n_in,
                              void* d_out, int out_size) {
    const float* values = (const float*)d_in[0];
    const float* masks  = (const float*)d_in[1];
    const float* deltas = (const float*)d_in[2];
    const float* emean  = (const float*)d_in[3];
    const float* xlocf  = (const float*)d_in[4];
    const float* wx     = (const float*)d_in[5];
    const float* bx     = (const float*)d_in[6];
    const float* Wh     = (const float*)d_in[7];
    const float* bh     = (const float*)d_in[8];
    const float* W_ih   = (const float*)d_in[9];
    const float* W_hh   = (const float*)d_in[10];
    const float* b_ih   = (const float*)d_in[11];
    const float* b_hh   = (const float*)d_in[12];
    float* out = (float*)d_out;

    cudaFuncSetAttribute(scan_mma_kernel,
                         cudaFuncAttributeMaxDynamicSharedMemorySize, SM_TOTAL);

    pack_w2_kernel<<<(1536 * 256) / 256, 256>>>(W_ih);
    pack_wtb_kernel<<<(2 * 32 * 96 * 512) / 256, 256>>>(W_ih, W_hh);
    xm_kernel<<<(BT * F_) / 256, 256>>>(values, masks, deltas, emean, xlocf, wx, bx);
    zero_h_kernel<<<(B_ * H_) / 256, 256>>>();
    // gamma_h = exp(-relu(deltas @ Wh^T + bh))
    gemm_f2_kernel<<<dim3(512 / 64, BT / 64), 256>>>(deltas, Wh, bh, 0);
    // gi_pre = xm @ W2^T + b_ih
    gemm_f2_kernel<<<dim3(1536 / 64, BT / 64), 256>>>(nullptr, nullptr, b_ih, 1);
    // persistent mma.sync scan (fp16 hi/lo split, ping-pong A buffers)
    scan_mma_kernel<<<dim3(32, 2), 128, SM_TOTAL>>>(b_hh, out);
}

// round 16
// speedup vs baseline: 2.2301x; 2.2301x over previous
#include <cuda_runtime.h>
#include <cuda_fp16.h>
#include <math.h>
#include <stdint.h>

#define B_ 256
#define T_ 256
#define F_ 128
#define H_ 512
#define BT (B_*T_)
#define NCTA 128

// ---------------- scratch (static __device__ allocations) -------------------
__device__ float g_xm[(size_t)BT * 256];        // [BT][256] = x_rep | m
__device__ float g_gamma_h[(size_t)BT * H_];    // [BT][512]
__device__ float g_gi[(size_t)BT * 1536];       // [BT][1536] gi_pre (+b_ih)
__device__ float g_W2[1536 * 256];              // [1536][256]
__device__ __half g_Wtb[2 * 32 * 96 * 512];     // [split][nb][c=g*16+jl][k] fp16
__device__ float g_h[2][B_ * H_];               // ping-pong hidden state (fp32)
__device__ __half g_abhi[2][B_ * H_];           // PING-PONG fp16 hi split of h.gamma
__device__ __half g_ablo[2][B_ * H_];           // PING-PONG fp16 lo split
__device__ int   g_flags[NCTA];
__device__ int   g_gen;

// ---------------- helpers ---------------------------------------------------
#define FMA2(d, a, b) asm("fma.rn.f32x2 %0, %1, %2, %0;" : "+l"(d) : "l"(a), "l"(b))
#define UNPK2(lo, hi, v) asm("mov.b64 {%0, %1}, %2;" : "=f"(lo), "=f"(hi) : "l"(v))

__device__ __forceinline__ uint32_t smem_to_u32(const void* p) {
    uint32_t a;
    asm("{ .reg .u64 t; cvta.to.shared.u64 t, %1; cvt.u32.u64 %0, t; }" : "=r"(a) : "l"(p));
    return a;
}

// warp-level fp16 MMA, fp32 accumulate (sm_80+, legal at plain compute_103)
#define MMA16816(d, a, b0v, b1v) \
    asm volatile("mma.sync.aligned.m16n8k16.row.col.f32.f16.f16.f32 " \
        "{%0,%1,%2,%3}, {%4,%5,%6,%7}, {%8,%9}, {%0,%1,%2,%3};" \
        : "+f"((d)[0]), "+f"((d)[1]), "+f"((d)[2]), "+f"((d)[3]) \
        : "r"((a)[0]), "r"((a)[1]), "r"((a)[2]), "r"((a)[3]), "r"(b0v), "r"(b1v))

#define LDSM4(r, addr) \
    asm volatile("ldmatrix.sync.aligned.m8n8.x4.shared.b16 {%0,%1,%2,%3}, [%4];" \
        : "=r"((r)[0]), "=r"((r)[1]), "=r"((r)[2]), "=r"((r)[3]) : "r"(addr))

// ---------------- pack kernels ---------------------------------------------
__global__ void __launch_bounds__(256) pack_w2_kernel(const float* __restrict__ W_ih) {
    int idx = blockIdx.x * 256 + threadIdx.x;       // 1536*256
    int row = idx >> 8, k = idx & 255;
    float v = (k < 128) ? W_ih[row * 768 + k] : W_ih[row * 768 + 512 + k];
    g_W2[idx] = v;
}

// fp16 split weights: g_Wtb[split][nb][c=g*16+jl][k], j = nb*16+jl
__global__ void __launch_bounds__(256) pack_wtb_kernel(const float* __restrict__ W_ih,
                                                       const float* __restrict__ W_hh) {
    int idx = blockIdx.x * 256 + threadIdx.x;       // 2*32*96*512
    int k = idx & 511;
    int r2 = idx >> 9;
    int c = r2 % 96;
    int t2 = r2 / 96;          // split*32 + nb
    int nb = t2 & 31;
    int split = t2 >> 5;
    int g = c >> 4, jl = c & 15;
    int j = nb * 16 + jl;
    float w = (g < 3) ? W_ih[(g * 512 + j) * 768 + 128 + k]
                      : W_hh[((g - 3) * 512 + j) * 512 + k];
    __half hi = __float2half_rn(w);
    if (split == 0) g_Wtb[idx] = hi;
    else            g_Wtb[idx] = __float2half_rn(w - __half2float(hi));
}

__global__ void __launch_bounds__(256) zero_h_kernel() {
    int i = blockIdx.x * 256 + threadIdx.x;         // B_*H_ = 131072
    g_h[0][i] = 0.0f;
    g_abhi[0][i] = __float2half_rn(0.0f);
    g_ablo[0][i] = __float2half_rn(0.0f);
    g_abhi[1][i] = __float2half_rn(0.0f);
    g_ablo[1][i] = __float2half_rn(0.0f);
    if (blockIdx.x == 0) {
        if (threadIdx.x < NCTA) g_flags[threadIdx.x] = 0;
        if (threadIdx.x == 0) g_gen = 0;
    }
}

// ---------------- elementwise: x_rep / m packing ----------------------------
__global__ void __launch_bounds__(256) xm_kernel(const float* __restrict__ values,
                          const float* __restrict__ masks,
                          const float* __restrict__ deltas,
                          const float* __restrict__ emean,
                          const float* __restrict__ xlocf,
                          const float* __restrict__ wx,
                          const float* __restrict__ bx) {
    int idx = blockIdx.x * 256 + threadIdx.x;       // BT*F
    int f = idx & 127;
    int r = idx >> 7;
    float d = deltas[idx];
    float a = d * wx[f] + bx[f];
    float gx = (a > 0.0f) ? expf(-a) : 1.0f;
    float m = masks[idx];
    float xh = gx * xlocf[idx] + (1.0f - gx) * emean[f];
    float xr = m * values[idx] + (1.0f - m) * xh;
    g_xm[(size_t)r * 256 + f] = xr;
    g_xm[(size_t)r * 256 + 128 + f] = m;
}

// ---------------- precompute GEMM (unchanged, proven) ------------------------
__global__ void __launch_bounds__(256) gemm_f2_kernel(const float* __restrict__ Ap,
                               const float* __restrict__ Wp,
                               const float* __restrict__ bias,
                               int which) {
    const float* __restrict__ A;
    const float* __restrict__ W;
    float* __restrict__ C;
    int N, K;
    if (which == 0) { A = Ap;   W = Wp;   C = g_gamma_h; N = 512;  K = 128; }
    else            { A = g_xm; W = g_W2; C = g_gi;      N = 1536; K = 256; }

    __shared__ __align__(16) float As[16 * 130];
    __shared__ __align__(16) float Bs[16 * 66];
    const int tid = threadIdx.x;
    const int m0 = blockIdx.y * 64;
    const int n0 = blockIdx.x * 64;
    const int lr = tid >> 2;
    const int kq = (tid & 3) << 2;
    const int ty = tid >> 4, tx = tid & 15;

    unsigned long long acc[4][2];
#pragma unroll
    for (int r = 0; r < 4; r++) { acc[r][0] = 0ull; acc[r][1] = 0ull; }

    for (int k0 = 0; k0 < K; k0 += 16) {
        float4 av = *(const float4*)(A + (size_t)(m0 + lr) * K + k0 + kq);
        float4 bv = *(const float4*)(W + (size_t)(n0 + lr) * K + k0 + kq);
        __syncthreads();
        As[(kq + 0) * 130 + 2 * lr] = av.x; As[(kq + 0) * 130 + 2 * lr + 1] = av.x;
        As[(kq + 1) * 130 + 2 * lr] = av.y; As[(kq + 1) * 130 + 2 * lr + 1] = av.y;
        As[(kq + 2) * 130 + 2 * lr] = av.z; As[(kq + 2) * 130 + 2 * lr + 1] = av.z;
        As[(kq + 3) * 130 + 2 * lr] = av.w; As[(kq + 3) * 130 + 2 * lr + 1] = av.w;
        Bs[(kq + 0) * 66 + lr] = bv.x;
        Bs[(kq + 1) * 66 + lr] = bv.y;
        Bs[(kq + 2) * 66 + lr] = bv.z;
        Bs[(kq + 3) * 66 + lr] = bv.w;
        __syncthreads();
#pragma unroll
        for (int kk = 0; kk < 16; kk++) {
            unsigned long long b01 = *(const unsigned long long*)&Bs[kk * 66 + tx * 4];
            unsigned long long b23 = *(const unsigned long long*)&Bs[kk * 66 + tx * 4 + 2];
#pragma unroll
            for (int r = 0; r < 4; r++) {
                unsigned long long ad =
                    *(const unsigned long long*)&As[kk * 130 + (ty * 4 + r) * 2];
                FMA2(acc[r][0], ad, b01);
                FMA2(acc[r][1], ad, b23);
            }
        }
    }
    const int n = n0 + tx * 4;
    float b0v = bias[n], b1v = bias[n + 1], b2v = bias[n + 2], b3v = bias[n + 3];
#pragma unroll
    for (int r = 0; r < 4; r++) {
        int m = m0 + ty * 4 + r;
        float4 v;
        UNPK2(v.x, v.y, acc[r][0]);
        UNPK2(v.z, v.w, acc[r][1]);
        v.x += b0v; v.y += b1v; v.z += b2v; v.w += b3v;
        if (which == 0) {
            v.x = (v.x > 0.0f) ? expf(-v.x) : 1.0f;
            v.y = (v.y > 0.0f) ? expf(-v.y) : 1.0f;
            v.z = (v.z > 0.0f) ? expf(-v.z) : 1.0f;
            v.w = (v.w > 0.0f) ? expf(-v.w) : 1.0f;
        }
        *(float4*)(C + (size_t)m * N + n) = v;
    }
}

// ---------------- persistent mma.sync scan kernel ----------------------------
// Grid (32, 4): nb = j-tile of 16 (96 packed gate-cols), quarter = 64 batch rows.
// 128 threads = 4 warps; warp w covers batch rows [b0+16w, +16) = ONE m16 tile.
// D[64 x 96] per CTA = A[64 x 512] @ W[96 x 512]^T, fp16 hi/lo split, 3 MMA
// terms issued TERM-MAJOR (12 independent accs between reuses -> latency hidden).
// W resident in SMEM (hi at 0, lo at 98304), XOR-swizzled for ldmatrix.
// A splits PING-PONG buffered (read parity t, write parity t+1).
// 128 CTAs, 192KB smem each -> 1 CTA/SM, all co-resident -> flag barrier safe.
#define SM_WLO 98304
#define SM_TOTAL 196608

// A-fragment load for k-chunk kc into ah/al (u32[4] each, one m16 tile)
#define LOADA(kc, ah, al) do { \
    int _k = (kc) * 16 + kb_l; \
    (ah)[0] = *(const uint32_t*)(abh + o0 + _k); \
    (ah)[1] = *(const uint32_t*)(abh + o0b + _k); \
    (ah)[2] = *(const uint32_t*)(abh + o0 + _k + 8); \
    (ah)[3] = *(const uint32_t*)(abh + o0b + _k + 8); \
    (al)[0] = *(const uint32_t*)(abl + o0 + _k); \
    (al)[1] = *(const uint32_t*)(abl + o0b + _k); \
    (al)[2] = *(const uint32_t*)(abl + o0 + _k + 8); \
    (al)[3] = *(const uint32_t*)(abl + o0b + _k + 8); \
} while (0)

__global__ void __launch_bounds__(128)
scan_mma_kernel(const float* __restrict__ b_hh, float* __restrict__ out) {
    extern __shared__ char smem[];
    const uint32_t sb = smem_to_u32(smem);
    const int tid = threadIdx.x;
    const int lane = tid & 31;
    const int wid = tid >> 5;
    const int nb = blockIdx.x;
    const int quarter = blockIdx.y;
    const int b0 = quarter * 64;
    const int cta = quarter * 32 + nb;

    // ---- load resident W (hi/lo) into swizzled SMEM ----
    {
        const __half* Whi = g_Wtb + (size_t)nb * 49152;
        const __half* Wlo = g_Wtb + (size_t)(32 + nb) * 49152;
        for (int i = tid; i < 96 * 512; i += 128) {
            int n = i >> 9, k = i & 511;
            uint32_t boff = (uint32_t)(n * 1024 + (((k >> 3) ^ (n & 7)) << 4) + (k & 7) * 2);
            *(__half*)(smem + boff) = Whi[i];
            *(__half*)(smem + SM_WLO + boff) = Wlo[i];
        }
    }
    __syncthreads();

    // ---- hoisted lane constants ----
    const int rowA0 = b0 + wid * 16 + (lane >> 2);   // this warp's m16 tile
    const size_t o0  = (size_t)rowA0 * 512;
    const size_t o0b = (size_t)(rowA0 + 8) * 512;
    const int kb_l = (lane & 3) << 1;

    // ldmatrix lane addressing: n' = p*16 + (lane&7) + ((lane>>4)<<3)
    const int nlane = (lane & 7) + ((lane >> 4) << 3);
    const int kl = (lane >> 3) & 1;
    const int nmask = nlane & 7;
    uint32_t bbase[6];
#pragma unroll
    for (int p = 0; p < 6; p++)
        bbase[p] = sb + (uint32_t)((p * 16 + nlane) * 1024);

    // epilogue hoists: biases per (tp, lo)
    float biasv[2][2][3];
#pragma unroll
    for (int tp = 0; tp < 2; tp++)
#pragma unroll
        for (int lo = 0; lo < 2; lo++) {
            int gj = nb * 16 + ((lane & 3) << 1) + (tp << 3) + lo;
            biasv[tp][lo][0] = b_hh[gj];
            biasv[tp][lo][1] = b_hh[512 + gj];
            biasv[tp][lo][2] = b_hh[1024 + gj];
        }

    for (int t = 0; t < T_; t++) {
        const __half* __restrict__ abh = g_abhi[t & 1];
        const __half* __restrict__ abl = g_ablo[t & 1];
        __half* __restrict__ abh_w = g_abhi[(t + 1) & 1];
        __half* __restrict__ abl_w = g_ablo[(t + 1) & 1];

        float acc[12][4];
#pragma unroll
        for (int nt = 0; nt < 12; nt++) {
            acc[nt][0] = 0.0f; acc[nt][1] = 0.0f;
            acc[nt][2] = 0.0f; acc[nt][3] = 0.0f;
        }

        uint32_t Ah[2][4], Al[2][4];
        LOADA(0, Ah[0], Al[0]);

#pragma unroll 2
        for (int kc = 0; kc < 32; kc++) {
            const int cb = kc & 1;
            uint32_t Bh[6][4], Bl[6][4];
            const uint32_t koff = (uint32_t)((((kc << 1) | kl) ^ nmask) << 4);
#pragma unroll
            for (int p = 0; p < 6; p++) {
                LDSM4(Bh[p], bbase[p] + koff);
                LDSM4(Bl[p], bbase[p] + SM_WLO + koff);
            }
            if (kc < 31) LOADA(kc + 1, Ah[cb ^ 1], Al[cb ^ 1]);
            // term-major: 12 independent accs between reuses of any acc
#pragma unroll
            for (int nt = 0; nt < 12; nt++) {
                const int p = nt >> 1, q = (nt & 1) << 1;
                MMA16816(acc[nt], Ah[cb], Bh[p][q], Bh[p][q + 1]);
            }
#pragma unroll
            for (int nt = 0; nt < 12; nt++) {
                const int p = nt >> 1, q = (nt & 1) << 1;
                MMA16816(acc[nt], Al[cb], Bh[p][q], Bh[p][q + 1]);
            }
#pragma unroll
            for (int nt = 0; nt < 12; nt++) {
                const int p = nt >> 1, q = (nt & 1) << 1;
                MMA16816(acc[nt], Ah[cb], Bl[p][q], Bl[p][q + 1]);
            }
        }

        // ---- epilogue: thread-local gates, state update, next-step A write ----
        const float* __restrict__ hin = g_h[t & 1];
        float* __restrict__ hout = g_h[(t + 1) & 1];
#pragma unroll
        for (int mh = 0; mh < 2; mh++) {
            const int b = rowA0 + mh * 8;
            const size_t ridx = (size_t)b * T_ + t;
            const float* __restrict__ gi = g_gi + ridx * 1536;
            const float* __restrict__ gr = g_gamma_h + ridx * 512;
#pragma unroll
            for (int tp = 0; tp < 2; tp++) {
                const int jl0 = ((lane & 3) << 1) + (tp << 3);
                const int gj0 = nb * 16 + jl0;
                float hv2[2];
#pragma unroll
                for (int lo = 0; lo < 2; lo++) {
                    const int gj = gj0 + lo;
                    const int rg = mh * 2 + lo;
                    float u0 = acc[tp][rg];
                    float u1 = acc[2 + tp][rg];
                    float u2 = acc[4 + tp][rg];
                    float u3 = acc[6 + tp][rg];
                    float u4 = acc[8 + tp][rg];
                    float u5 = acc[10 + tp][rg];
                    float ir  = gi[gj] + u0;
                    float iz  = gi[512 + gj] + u1;
                    float in_ = gi[1024 + gj] + u2;
                    float hr_ = u3 + biasv[tp][lo][0];
                    float hz  = u4 + biasv[tp][lo][1];
                    float hn  = u5 + biasv[tp][lo][2];
                    float hd = hin[(size_t)b * 512 + gj] * gr[gj];
                    float r = 1.0f / (1.0f + expf(-(ir + hr_)));
                    float z = 1.0f / (1.0f + expf(-(iz + hz)));
                    float n = tanhf(in_ + r * hn);
                    float hvn = (1.0f - z) * n + z * hd;
                    hout[(size_t)b * 512 + gj] = hvn;
                    out[ridx * 512 + gj] = hvn;
                    if (t == T_ - 1)
                        out[(size_t)BT * 512 + (size_t)b * 512 + gj] = hvn;
                    hv2[lo] = hvn;
                }
                if (t < T_ - 1) {
                    const float* grn = g_gamma_h + (ridx + 1) * 512;
                    float x0 = hv2[0] * grn[gj0];
                    float x1 = hv2[1] * grn[gj0 + 1];
                    __half h0 = __float2half_rn(x0);
                    __half h1 = __float2half_rn(x1);
                    float r0 = x0 - __half2float(h0);
                    float r1 = x1 - __half2float(h1);
                    __half l0 = __float2half_rn(r0);
                    __half l1 = __float2half_rn(r1);
                    __half2 ph = __halves2half2(h0, h1);
                    __half2 pl = __halves2half2(l0, l1);
                    *(__half2*)(abh_w + (size_t)b * 512 + gj0) = ph;
                    *(__half2*)(abl_w + (size_t)b * 512 + gj0) = pl;
                }
            }
        }

        // ---- grid barrier (128 CTAs co-resident, flag protocol) ----
        if (t < T_ - 1) {
            __syncthreads();
            if (tid == 0) {
                __threadfence();
                ((volatile int*)g_flags)[cta] = t + 1;
            }
            if (cta == 0) {
                if (tid < NCTA) {
                    while (((volatile int*)g_flags)[tid] <= t) { }
                    __threadfence();
                }
            } else {
                if (tid == 0) {
                    while (*((volatile int*)&g_gen) <= t) { }
                    __threadfence();
                }
            }
            __syncthreads();
            if (cta == 0 && tid == 0) {
                *((volatile int*)&g_gen) = t + 1;
            }
        }
    }
}

// ---------------- launch ----------------------------------------------------
extern "C" void kernel_launch(void* const* d_in, const int* in_sizes, int n_in,
                              void* d_out, int out_size) {
    const float* values = (const float*)d_in[0];
    const float* masks  = (const float*)d_in[1];
    const float* deltas = (const float*)d_in[2];
    const float* emean  = (const float*)d_in[3];
    const float* xlocf  = (const float*)d_in[4];
    const float* wx     = (const float*)d_in[5];
    const float* bx     = (const float*)d_in[6];
    const float* Wh     = (const float*)d_in[7];
    const float* bh     = (const float*)d_in[8];
    const float* W_ih   = (const float*)d_in[9];
    const float* W_hh   = (const float*)d_in[10];
    const float* b_ih   = (const float*)d_in[11];
    const float* b_hh   = (const float*)d_in[12];
    float* out = (float*)d_out;

    cudaFuncSetAttribute(scan_mma_kernel,
                         cudaFuncAttributeMaxDynamicSharedMemorySize, SM_TOTAL);

    pack_w2_kernel<<<(1536 * 256) / 256, 256>>>(W_ih);
    pack_wtb_kernel<<<(2 * 32 * 96 * 512) / 256, 256>>>(W_ih, W_hh);
    xm_kernel<<<(BT * F_) / 256, 256>>>(values, masks, deltas, emean, xlocf, wx, bx);
    zero_h_kernel<<<(B_ * H_) / 256, 256>>>();
    // gamma_h = exp(-relu(deltas @ Wh^T + bh))
    gemm_f2_kernel<<<dim3(512 / 64, BT / 64), 256>>>(deltas, Wh, bh, 0);
    // gi_pre = xm @ W2^T + b_ih
    gemm_f2_kernel<<<dim3(1536 / 64, BT / 64), 256>>>(nullptr, nullptr, b_ih, 1);
    // persistent mma.sync scan (fp16 split, ping-pong A, 128 CTAs)
    scan_mma_kernel<<<dim3(32, 4), 128, SM_TOTAL>>>(b_hh, out);
}

// round 17
// speedup vs baseline: 2.5541x; 1.1453x over previous
#include <cuda_runtime.h>
#include <cuda_fp16.h>
#include <math.h>
#include <stdint.h>

#define B_ 256
#define T_ 256
#define F_ 128
#define H_ 512
#define BT (B_*T_)
#define NCTA 128

// ---------------- scratch (static __device__ allocations) -------------------
__device__ float g_gamma_h[(size_t)BT * H_];    // [BT][512]
__device__ float g_gi[(size_t)BT * 1536];       // [BT][1536] gi_pre (+b_ih)
__device__ __half g_xmh[(size_t)BT * 256];      // fp16 hi split of [x_rep | m]
__device__ __half g_xml[(size_t)BT * 256];      // fp16 lo split
__device__ __half g_W2h[1536 * 256];            // fp16 hi split of W2
__device__ __half g_W2l[1536 * 256];            // fp16 lo split
__device__ __half g_Wtb[2 * 32 * 96 * 512];     // [split][nb][c=g*16+jl][k] fp16
__device__ float g_h[2][B_ * H_];               // ping-pong hidden state (fp32)
__device__ __half g_abhi[2][B_ * H_];           // PING-PONG fp16 hi split of h.gamma
__device__ __half g_ablo[2][B_ * H_];           // PING-PONG fp16 lo split
__device__ int   g_flags[NCTA];
__device__ int   g_gen;

// ---------------- helpers ---------------------------------------------------
#define FMA2(d, a, b) asm("fma.rn.f32x2 %0, %1, %2, %0;" : "+l"(d) : "l"(a), "l"(b))
#define UNPK2(lo, hi, v) asm("mov.b64 {%0, %1}, %2;" : "=f"(lo), "=f"(hi) : "l"(v))

__device__ __forceinline__ uint32_t smem_to_u32(const void* p) {
    uint32_t a;
    asm("{ .reg .u64 t; cvta.to.shared.u64 t, %1; cvt.u32.u64 %0, t; }" : "=r"(a) : "l"(p));
    return a;
}

// warp-level fp16 MMA, fp32 accumulate (sm_80+, legal at plain compute_103)
#define MMA16816(d, a, b0v, b1v) \
    asm volatile("mma.sync.aligned.m16n8k16.row.col.f32.f16.f16.f32 " \
        "{%0,%1,%2,%3}, {%4,%5,%6,%7}, {%8,%9}, {%0,%1,%2,%3};" \
        : "+f"((d)[0]), "+f"((d)[1]), "+f"((d)[2]), "+f"((d)[3]) \
        : "r"((a)[0]), "r"((a)[1]), "r"((a)[2]), "r"((a)[3]), "r"(b0v), "r"(b1v))

#define LDSM4(r, addr) \
    asm volatile("ldmatrix.sync.aligned.m8n8.x4.shared.b16 {%0,%1,%2,%3}, [%4];" \
        : "=r"((r)[0]), "=r"((r)[1]), "=r"((r)[2]), "=r"((r)[3]) : "r"(addr))

// ---------------- pack kernels ---------------------------------------------
// fp16 hi/lo split of W2 rows: [x(0:128) | m-part of W_ih(640:768) mapped to 128:256)]
__global__ void __launch_bounds__(256) pack_w2_kernel(const float* __restrict__ W_ih) {
    int idx = blockIdx.x * 256 + threadIdx.x;       // 1536*256
    int row = idx >> 8, k = idx & 255;
    float v = (k < 128) ? W_ih[row * 768 + k] : W_ih[row * 768 + 512 + k];
    __half hi = __float2half_rn(v);
    g_W2h[idx] = hi;
    g_W2l[idx] = __float2half_rn(v - __half2float(hi));
}

// fp16 split weights: g_Wtb[split][nb][c=g*16+jl][k], j = nb*16+jl
__global__ void __launch_bounds__(256) pack_wtb_kernel(const float* __restrict__ W_ih,
                                                       const float* __restrict__ W_hh) {
    int idx = blockIdx.x * 256 + threadIdx.x;       // 2*32*96*512
    int k = idx & 511;
    int r2 = idx >> 9;
    int c = r2 % 96;
    int t2 = r2 / 96;          // split*32 + nb
    int nb = t2 & 31;
    int split = t2 >> 5;
    int g = c >> 4, jl = c & 15;
    int j = nb * 16 + jl;
    float w = (g < 3) ? W_ih[(g * 512 + j) * 768 + 128 + k]
                      : W_hh[((g - 3) * 512 + j) * 512 + k];
    __half hi = __float2half_rn(w);
    if (split == 0) g_Wtb[idx] = hi;
    else            g_Wtb[idx] = __float2half_rn(w - __half2float(hi));
}

__global__ void __launch_bounds__(256) zero_h_kernel() {
    int i = blockIdx.x * 256 + threadIdx.x;         // B_*H_ = 131072
    g_h[0][i] = 0.0f;
    g_abhi[0][i] = __float2half_rn(0.0f);
    g_ablo[0][i] = __float2half_rn(0.0f);
    g_abhi[1][i] = __float2half_rn(0.0f);
    g_ablo[1][i] = __float2half_rn(0.0f);
    if (blockIdx.x == 0) {
        if (threadIdx.x < NCTA) g_flags[threadIdx.x] = 0;
        if (threadIdx.x == 0) g_gen = 0;
    }
}

// ---------------- elementwise: x_rep / m packing (fp16 hi/lo splits) ---------
__global__ void __launch_bounds__(256) xm_kernel(const float* __restrict__ values,
                          const float* __restrict__ masks,
                          const float* __restrict__ deltas,
                          const float* __restrict__ emean,
                          const float* __restrict__ xlocf,
                          const float* __restrict__ wx,
                          const float* __restrict__ bx) {
    int idx = blockIdx.x * 256 + threadIdx.x;       // BT*F
    int f = idx & 127;
    int r = idx >> 7;
    float d = deltas[idx];
    float a = d * wx[f] + bx[f];
    float gx = (a > 0.0f) ? expf(-a) : 1.0f;
    float m = masks[idx];
    float xh = gx * xlocf[idx] + (1.0f - gx) * emean[f];
    float xr = m * values[idx] + (1.0f - m) * xh;
    __half hi = __float2half_rn(xr);
    __half lo = __float2half_rn(xr - __half2float(hi));
    g_xmh[(size_t)r * 256 + f] = hi;
    g_xml[(size_t)r * 256 + f] = lo;
    g_xmh[(size_t)r * 256 + 128 + f] = __float2half_rn(m);   // exact (0/1)
    g_xml[(size_t)r * 256 + 128 + f] = __float2half_rn(0.0f);
}

// ---------------- gamma precompute GEMM (fp32, proven) -----------------------
// gamma_h = exp(-relu(deltas @ Wh^T + bh)) : [BT,128] x [512,128]^T
__global__ void __launch_bounds__(256) gemm_f2_kernel(const float* __restrict__ A,
                               const float* __restrict__ W,
                               const float* __restrict__ bias) {
    float* __restrict__ C = g_gamma_h;
    const int N = 512, K = 128;
    __shared__ __align__(16) float As[16 * 130];
    __shared__ __align__(16) float Bs[16 * 66];
    const int tid = threadIdx.x;
    const int m0 = blockIdx.y * 64;
    const int n0 = blockIdx.x * 64;
    const int lr = tid >> 2;
    const int kq = (tid & 3) << 2;
    const int ty = tid >> 4, tx = tid & 15;

    unsigned long long acc[4][2];
#pragma unroll
    for (int r = 0; r < 4; r++) { acc[r][0] = 0ull; acc[r][1] = 0ull; }

    for (int k0 = 0; k0 < K; k0 += 16) {
        float4 av = *(const float4*)(A + (size_t)(m0 + lr) * K + k0 + kq);
        float4 bv = *(const float4*)(W + (size_t)(n0 + lr) * K + k0 + kq);
        __syncthreads();
        As[(kq + 0) * 130 + 2 * lr] = av.x; As[(kq + 0) * 130 + 2 * lr + 1] = av.x;
        As[(kq + 1) * 130 + 2 * lr] = av.y; As[(kq + 1) * 130 + 2 * lr + 1] = av.y;
        As[(kq + 2) * 130 + 2 * lr] = av.z; As[(kq + 2) * 130 + 2 * lr + 1] = av.z;
        As[(kq + 3) * 130 + 2 * lr] = av.w; As[(kq + 3) * 130 + 2 * lr + 1] = av.w;
        Bs[(kq + 0) * 66 + lr] = bv.x;
        Bs[(kq + 1) * 66 + lr] = bv.y;
        Bs[(kq + 2) * 66 + lr] = bv.z;
        Bs[(kq + 3) * 66 + lr] = bv.w;
        __syncthreads();
#pragma unroll
        for (int kk = 0; kk < 16; kk++) {
            unsigned long long b01 = *(const unsigned long long*)&Bs[kk * 66 + tx * 4];
            unsigned long long b23 = *(const unsigned long long*)&Bs[kk * 66 + tx * 4 + 2];
#pragma unroll
            for (int r = 0; r < 4; r++) {
                unsigned long long ad =
                    *(const unsigned long long*)&As[kk * 130 + (ty * 4 + r) * 2];
                FMA2(acc[r][0], ad, b01);
                FMA2(acc[r][1], ad, b23);
            }
        }
    }
    const int n = n0 + tx * 4;
    float b0v = bias[n], b1v = bias[n + 1], b2v = bias[n + 2], b3v = bias[n + 3];
#pragma unroll
    for (int r = 0; r < 4; r++) {
        int m = m0 + ty * 4 + r;
        float4 v;
        UNPK2(v.x, v.y, acc[r][0]);
        UNPK2(v.z, v.w, acc[r][1]);
        v.x += b0v; v.y += b1v; v.z += b2v; v.w += b3v;
        v.x = (v.x > 0.0f) ? expf(-v.x) : 1.0f;
        v.y = (v.y > 0.0f) ? expf(-v.y) : 1.0f;
        v.z = (v.z > 0.0f) ? expf(-v.z) : 1.0f;
        v.w = (v.w > 0.0f) ? expf(-v.w) : 1.0f;
        *(float4*)(C + (size_t)m * N + n) = v;
    }
}

// ---------------- gi precompute GEMM on tensor cores -------------------------
// g_gi[BT,1536] = xm[BT,256] @ W2[1536,256]^T + b_ih, fp16 hi/lo split, 3 terms.
// Grid (16, 1024): nb = 96-col tile of 1536, m-tile = 64 rows of BT.
// 128 threads = 4 warps, warp = one m16 tile. B tile (hi+lo) = 96KB smem.
#define GI_SLO 49152
#define GI_SM_TOTAL 98304

__global__ void __launch_bounds__(128)
gi_mma_kernel(const float* __restrict__ b_ih) {
    extern __shared__ char smem[];
    const uint32_t sb = smem_to_u32(smem);
    const int tid = threadIdx.x;
    const int lane = tid & 31;
    const int wid = tid >> 5;
    const int nb = blockIdx.x;            // 0..15
    const int mt0 = blockIdx.y * 64;      // row base

    // ---- load B tile (96 x 256, hi/lo) into swizzled SMEM (row stride 512B) --
    for (int i = tid; i < 96 * 256; i += 128) {
        int n = i >> 8, k = i & 255;
        uint32_t boff = (uint32_t)(n * 512 + (((k >> 3) ^ (n & 7)) << 4) + (k & 7) * 2);
        *(__half*)(smem + boff) = g_W2h[(size_t)(nb * 96 + n) * 256 + k];
        *(__half*)(smem + GI_SLO + boff) = g_W2l[(size_t)(nb * 96 + n) * 256 + k];
    }
    __syncthreads();

    const int rowA0 = mt0 + wid * 16 + (lane >> 2);
    const size_t o0  = (size_t)rowA0 * 256;
    const size_t o0b = (size_t)(rowA0 + 8) * 256;
    const int kb_l = (lane & 3) << 1;

    const int nlane = (lane & 7) + ((lane >> 4) << 3);
    const int kl = (lane >> 3) & 1;
    const int nmask = nlane & 7;
    uint32_t bbase[6];
#pragma unroll
    for (int p = 0; p < 6; p++)
        bbase[p] = sb + (uint32_t)((p * 16 + nlane) * 512);

    float acc[12][4];
#pragma unroll
    for (int nt = 0; nt < 12; nt++) {
        acc[nt][0] = 0.0f; acc[nt][1] = 0.0f; acc[nt][2] = 0.0f; acc[nt][3] = 0.0f;
    }

    const __half* __restrict__ abh = g_xmh;
    const __half* __restrict__ abl = g_xml;
    uint32_t Ah[2][4], Al[2][4];
    {
        int _k = kb_l;
        Ah[0][0] = *(const uint32_t*)(abh + o0 + _k);
        Ah[0][1] = *(const uint32_t*)(abh + o0b + _k);
        Ah[0][2] = *(const uint32_t*)(abh + o0 + _k + 8);
        Ah[0][3] = *(const uint32_t*)(abh + o0b + _k + 8);
        Al[0][0] = *(const uint32_t*)(abl + o0 + _k);
        Al[0][1] = *(const uint32_t*)(abl + o0b + _k);
        Al[0][2] = *(const uint32_t*)(abl + o0 + _k + 8);
        Al[0][3] = *(const uint32_t*)(abl + o0b + _k + 8);
    }

#pragma unroll 2
    for (int kc = 0; kc < 16; kc++) {
        const int cb = kc & 1;
        uint32_t Bh[6][4], Bl[6][4];
        const uint32_t koff = (uint32_t)((((kc << 1) | kl) ^ nmask) << 4);
#pragma unroll
        for (int p = 0; p < 6; p++) {
            LDSM4(Bh[p], bbase[p] + koff);
            LDSM4(Bl[p], bbase[p] + GI_SLO + koff);
        }
        if (kc < 15) {
            int _k = (kc + 1) * 16 + kb_l;
            Ah[cb ^ 1][0] = *(const uint32_t*)(abh + o0 + _k);
            Ah[cb ^ 1][1] = *(const uint32_t*)(abh + o0b + _k);
            Ah[cb ^ 1][2] = *(const uint32_t*)(abh + o0 + _k + 8);
            Ah[cb ^ 1][3] = *(const uint32_t*)(abh + o0b + _k + 8);
            Al[cb ^ 1][0] = *(const uint32_t*)(abl + o0 + _k);
            Al[cb ^ 1][1] = *(const uint32_t*)(abl + o0b + _k);
            Al[cb ^ 1][2] = *(const uint32_t*)(abl + o0 + _k + 8);
            Al[cb ^ 1][3] = *(const uint32_t*)(abl + o0b + _k + 8);
        }
#pragma unroll
        for (int nt = 0; nt < 12; nt++) {
            const int p = nt >> 1, q = (nt & 1) << 1;
            MMA16816(acc[nt], Ah[cb], Bh[p][q], Bh[p][q + 1]);
        }
#pragma unroll
        for (int nt = 0; nt < 12; nt++) {
            const int p = nt >> 1, q = (nt & 1) << 1;
            MMA16816(acc[nt], Al[cb], Bh[p][q], Bh[p][q + 1]);
        }
#pragma unroll
        for (int nt = 0; nt < 12; nt++) {
            const int p = nt >> 1, q = (nt & 1) << 1;
            MMA16816(acc[nt], Ah[cb], Bl[p][q], Bl[p][q + 1]);
        }
    }

    // ---- epilogue: + b_ih, write g_gi ----
#pragma unroll
    for (int mh = 0; mh < 2; mh++) {
        const int row = rowA0 + mh * 8;
        float* __restrict__ gout = g_gi + (size_t)row * 1536;
#pragma unroll
        for (int nt = 0; nt < 12; nt++) {
            const int col = nb * 96 + nt * 8 + (lane & 3) * 2;
            float2 v;
            v.x = acc[nt][mh * 2 + 0] + b_ih[col];
            v.y = acc[nt][mh * 2 + 1] + b_ih[col + 1];
            *(float2*)(gout + col) = v;
        }
    }
}

// ---------------- persistent mma.sync scan kernel (R16, proven) --------------
#define SM_WLO 98304
#define SM_TOTAL 196608

#define LOADA(kc, ah, al) do { \
    int _k = (kc) * 16 + kb_l; \
    (ah)[0] = *(const uint32_t*)(abh + o0 + _k); \
    (ah)[1] = *(const uint32_t*)(abh + o0b + _k); \
    (ah)[2] = *(const uint32_t*)(abh + o0 + _k + 8); \
    (ah)[3] = *(const uint32_t*)(abh + o0b + _k + 8); \
    (al)[0] = *(const uint32_t*)(abl + o0 + _k); \
    (al)[1] = *(const uint32_t*)(abl + o0b + _k); \
    (al)[2] = *(const uint32_t*)(abl + o0 + _k + 8); \
    (al)[3] = *(const uint32_t*)(abl + o0b + _k + 8); \
} while (0)

__global__ void __launch_bounds__(128)
scan_mma_kernel(const float* __restrict__ b_hh, float* __restrict__ out) {
    extern __shared__ char smem[];
    const uint32_t sb = smem_to_u32(smem);
    const int tid = threadIdx.x;
    const int lane = tid & 31;
    const int wid = tid >> 5;
    const int nb = blockIdx.x;
    const int quarter = blockIdx.y;
    const int b0 = quarter * 64;
    const int cta = quarter * 32 + nb;

    {
        const __half* Whi = g_Wtb + (size_t)nb * 49152;
        const __half* Wlo = g_Wtb + (size_t)(32 + nb) * 49152;
        for (int i = tid; i < 96 * 512; i += 128) {
            int n = i >> 9, k = i & 511;
            uint32_t boff = (uint32_t)(n * 1024 + (((k >> 3) ^ (n & 7)) << 4) + (k & 7) * 2);
            *(__half*)(smem + boff) = Whi[i];
            *(__half*)(smem + SM_WLO + boff) = Wlo[i];
        }
    }
    __syncthreads();

    const int rowA0 = b0 + wid * 16 + (lane >> 2);
    const size_t o0  = (size_t)rowA0 * 512;
    const size_t o0b = (size_t)(rowA0 + 8) * 512;
    const int kb_l = (lane & 3) << 1;

    const int nlane = (lane & 7) + ((lane >> 4) << 3);
    const int kl = (lane >> 3) & 1;
    const int nmask = nlane & 7;
    uint32_t bbase[6];
#pragma unroll
    for (int p = 0; p < 6; p++)
        bbase[p] = sb + (uint32_t)((p * 16 + nlane) * 1024);

    float biasv[2][2][3];
#pragma unroll
    for (int tp = 0; tp < 2; tp++)
#pragma unroll
        for (int lo = 0; lo < 2; lo++) {
            int gj = nb * 16 + ((lane & 3) << 1) + (tp << 3) + lo;
            biasv[tp][lo][0] = b_hh[gj];
            biasv[tp][lo][1] = b_hh[512 + gj];
            biasv[tp][lo][2] = b_hh[1024 + gj];
        }

    for (int t = 0; t < T_; t++) {
        const __half* __restrict__ abh = g_abhi[t & 1];
        const __half* __restrict__ abl = g_ablo[t & 1];
        __half* __restrict__ abh_w = g_abhi[(t + 1) & 1];
        __half* __restrict__ abl_w = g_ablo[(t + 1) & 1];

        float acc[12][4];
#pragma unroll
        for (int nt = 0; nt < 12; nt++) {
            acc[nt][0] = 0.0f; acc[nt][1] = 0.0f;
            acc[nt][2] = 0.0f; acc[nt][3] = 0.0f;
        }

        uint32_t Ah[2][4], Al[2][4];
        LOADA(0, Ah[0], Al[0]);

#pragma unroll 2
        for (int kc = 0; kc < 32; kc++) {
            const int cb = kc & 1;
            uint32_t Bh[6][4], Bl[6][4];
            const uint32_t koff = (uint32_t)((((kc << 1) | kl) ^ nmask) << 4);
#pragma unroll
            for (int p = 0; p < 6; p++) {
                LDSM4(Bh[p], bbase[p] + koff);
                LDSM4(Bl[p], bbase[p] + SM_WLO + koff);
            }
            if (kc < 31) LOADA(kc + 1, Ah[cb ^ 1], Al[cb ^ 1]);
#pragma unroll
            for (int nt = 0; nt < 12; nt++) {
                const int p = nt >> 1, q = (nt & 1) << 1;
                MMA16816(acc[nt], Ah[cb], Bh[p][q], Bh[p][q + 1]);
            }
#pragma unroll
            for (int nt = 0; nt < 12; nt++) {
                const int p = nt >> 1, q = (nt & 1) << 1;
                MMA16816(acc[nt], Al[cb], Bh[p][q], Bh[p][q + 1]);
            }
#pragma unroll
            for (int nt = 0; nt < 12; nt++) {
                const int p = nt >> 1, q = (nt & 1) << 1;
                MMA16816(acc[nt], Ah[cb], Bl[p][q], Bl[p][q + 1]);
            }
        }

        const float* __restrict__ hin = g_h[t & 1];
        float* __restrict__ hout = g_h[(t + 1) & 1];
#pragma unroll
        for (int mh = 0; mh < 2; mh++) {
            const int b = rowA0 + mh * 8;
            const size_t ridx = (size_t)b * T_ + t;
            const float* __restrict__ gi = g_gi + ridx * 1536;
            const float* __restrict__ gr = g_gamma_h + ridx * 512;
#pragma unroll
            for (int tp = 0; tp < 2; tp++) {
                const int jl0 = ((lane & 3) << 1) + (tp << 3);
                const int gj0 = nb * 16 + jl0;
                float hv2[2];
#pragma unroll
                for (int lo = 0; lo < 2; lo++) {
                    const int gj = gj0 + lo;
                    const int rg = mh * 2 + lo;
                    float u0 = acc[tp][rg];
                    float u1 = acc[2 + tp][rg];
                    float u2 = acc[4 + tp][rg];
                    float u3 = acc[6 + tp][rg];
                    float u4 = acc[8 + tp][rg];
                    float u5 = acc[10 + tp][rg];
                    float ir  = gi[gj] + u0;
                    float iz  = gi[512 + gj] + u1;
                    float in_ = gi[1024 + gj] + u2;
                    float hr_ = u3 + biasv[tp][lo][0];
                    float hz  = u4 + biasv[tp][lo][1];
                    float hn  = u5 + biasv[tp][lo][2];
                    float hd = hin[(size_t)b * 512 + gj] * gr[gj];
                    float r = 1.0f / (1.0f + expf(-(ir + hr_)));
                    float z = 1.0f / (1.0f + expf(-(iz + hz)));
                    float n = tanhf(in_ + r * hn);
                    float hvn = (1.0f - z) * n + z * hd;
                    hout[(size_t)b * 512 + gj] = hvn;
                    out[ridx * 512 + gj] = hvn;
                    if (t == T_ - 1)
                        out[(size_t)BT * 512 + (size_t)b * 512 + gj] = hvn;
                    hv2[lo] = hvn;
                }
                if (t < T_ - 1) {
                    const float* grn = g_gamma_h + (ridx + 1) * 512;
                    float x0 = hv2[0] * grn[gj0];
                    float x1 = hv2[1] * grn[gj0 + 1];
                    __half h0 = __float2half_rn(x0);
                    __half h1 = __float2half_rn(x1);
                    float r0 = x0 - __half2float(h0);
                    float r1 = x1 - __half2float(h1);
                    __half l0 = __float2half_rn(r0);
                    __half l1 = __float2half_rn(r1);
                    __half2 ph = __halves2half2(h0, h1);
                    __half2 pl = __halves2half2(l0, l1);
                    *(__half2*)(abh_w + (size_t)b * 512 + gj0) = ph;
                    *(__half2*)(abl_w + (size_t)b * 512 + gj0) = pl;
                }
            }
        }

        if (t < T_ - 1) {
            __syncthreads();
            if (tid == 0) {
                __threadfence();
                ((volatile int*)g_flags)[cta] = t + 1;
            }
            if (cta == 0) {
                if (tid < NCTA) {
                    while (((volatile int*)g_flags)[tid] <= t) { }
                    __threadfence();
                }
            } else {
                if (tid == 0) {
                    while (*((volatile int*)&g_gen) <= t) { }
                    __threadfence();
                }
            }
            __syncthreads();
            if (cta == 0 && tid == 0) {
                *((volatile int*)&g_gen) = t + 1;
            }
        }
    }
}

// ---------------- launch ----------------------------------------------------
extern "C" void kernel_launch(void* const* d_in, const int* in_sizes, int n_in,
                              void* d_out, int out_size) {
    const float* values = (const float*)d_in[0];
    const float* masks  = (const float*)d_in[1];
    const float* deltas = (const float*)d_in[2];
    const float* emean  = (const float*)d_in[3];
    const float* xlocf  = (const float*)d_in[4];
    const float* wx     = (const float*)d_in[5];
    const float* bx     = (const float*)d_in[6];
    const float* Wh     = (const float*)d_in[7];
    const float* bh     = (const float*)d_in[8];
    const float* W_ih   = (const float*)d_in[9];
    const float* W_hh   = (const float*)d_in[10];
    const float* b_ih   = (const float*)d_in[11];
    const float* b_hh   = (const float*)d_in[12];
    float* out = (float*)d_out;

    cudaFuncSetAttribute(scan_mma_kernel,
                         cudaFuncAttributeMaxDynamicSharedMemorySize, SM_TOTAL);
    cudaFuncSetAttribute(gi_mma_kernel,
                         cudaFuncAttributeMaxDynamicSharedMemorySize, GI_SM_TOTAL);

    pack_w2_kernel<<<(1536 * 256) / 256, 256>>>(W_ih);
    pack_wtb_kernel<<<(2 * 32 * 96 * 512) / 256, 256>>>(W_ih, W_hh);
    xm_kernel<<<(BT * F_) / 256, 256>>>(values, masks, deltas, emean, xlocf, wx, bx);
    zero_h_kernel<<<(B_ * H_) / 256, 256>>>();
    // gamma_h = exp(-relu(deltas @ Wh^T + bh)) (fp32 SIMT path)
    gemm_f2_kernel<<<dim3(512 / 64, BT / 64), 256>>>(deltas, Wh, bh);
    // gi_pre = xm @ W2^T + b_ih (fp16-split tensor path)
    gi_mma_kernel<<<dim3(16, 1024), 128, GI_SM_TOTAL>>>(b_ih);
    // persistent mma.sync scan (fp16 split, ping-pong A, 128 CTAs)
    scan_mma_kernel<<<dim3(32, 4), 128, SM_TOTAL>>>(b_hh, out);
}